// round 5
// baseline (speedup 1.0000x reference)
#include <cuda_runtime.h>
#include <cstdint>
#include <cstddef>

// ---------------------------------------------------------------------------
// BertBiLstmCrf: BiLSTM(768->2x384) -> FC(768->12) -> Viterbi decode
// B=64, T=512, H=768, LH=384, L=12
// Inputs (metadata order):
//  0 hidden_states (64,512,768) f32
//  1 h0 (2,64,384)  2 c0 (2,64,384)
//  3 w_ih_f (1536,768)  4 w_hh_f (1536,384)  5 b_ih_f (1536)  6 b_hh_f (1536)
//  7 w_ih_b (1536,768)  8 w_hh_b (1536,384)  9 b_ih_b (1536) 10 b_hh_b (1536)
// 11 fc_w (12,768) 12 fc_b (12) 13 transitions (12,12) 14 start_idx 15 end_idx
// Output: [score(64) ; path(64*512)] as float32
// ---------------------------------------------------------------------------

#define NEGV (-1000.0f)

// Scratch (static __device__ arrays; no allocations anywhere)
__device__ float        g_pre[(size_t)32768 * 3072];   // gate pre-activations [t*64+b][dir*1536+row]
__device__ float        g_h[2][512][384][64];          // [dir][t][k][b]  (transposed for coalescing)
__device__ float        g_feat[512][64][12];           // emissions
__device__ unsigned char g_ptr[511][64][12];           // viterbi backpointers
__device__ unsigned int g_bar[8];                      // barriers: [dir*4 + batch_group]

__global__ void k_init() {
    if (threadIdx.x < 8) g_bar[threadIdx.x] = 0u;
}

// ---------------------------------------------------------------------------
// Kernel 1: input-projection SGEMM.
// C[m][n] = sum_k A[m][k]*Wrow[n][k] + bias[n],  m = t*64+b (A row = hs[b][t]),
// n<1536 -> forward weights, n>=1536 -> backward weights.
// 128x128 tile, BK=8, 256 threads, 8x8 per thread, global prefetch.
// ---------------------------------------------------------------------------
__global__ __launch_bounds__(256) void k_gemm(
    const float* __restrict__ hs,
    const float* __restrict__ wf, const float* __restrict__ wb,
    const float* __restrict__ bif, const float* __restrict__ bhf,
    const float* __restrict__ bib, const float* __restrict__ bhb)
{
    __shared__ float As[8][128];
    __shared__ float Bs[8][128];
    const int tid = threadIdx.x;
    const int m0 = blockIdx.y * 128;
    const int n0 = blockIdx.x * 128;

    const int lr = tid >> 1;           // tile row 0..127
    const int lk = (tid & 1) * 4;      // k offset 0 or 4
    const int m  = m0 + lr;
    const float* arow = hs + ((size_t)(m & 63) * 512 + (m >> 6)) * 768 + lk;
    const int nrow = n0 + lr;
    const float* brow = (nrow < 1536) ? (wf + (size_t)nrow * 768 + lk)
                                      : (wb + (size_t)(nrow - 1536) * 768 + lk);

    const int ty = tid >> 4, tx = tid & 15;

    float acc[8][8];
#pragma unroll
    for (int i = 0; i < 8; i++)
#pragma unroll
        for (int j = 0; j < 8; j++) acc[i][j] = 0.f;

    float4 a4 = *(const float4*)(arow);
    float4 b4 = *(const float4*)(brow);

    for (int k0 = 0; k0 < 768; k0 += 8) {
        As[lk+0][lr] = a4.x; As[lk+1][lr] = a4.y; As[lk+2][lr] = a4.z; As[lk+3][lr] = a4.w;
        Bs[lk+0][lr] = b4.x; Bs[lk+1][lr] = b4.y; Bs[lk+2][lr] = b4.z; Bs[lk+3][lr] = b4.w;
        __syncthreads();
        if (k0 + 8 < 768) {
            a4 = *(const float4*)(arow + k0 + 8);
            b4 = *(const float4*)(brow + k0 + 8);
        }
#pragma unroll
        for (int kk = 0; kk < 8; kk++) {
            float af[8], bf[8];
            *(float4*)(af)     = *(const float4*)&As[kk][ty*8];
            *(float4*)(af + 4) = *(const float4*)&As[kk][ty*8 + 4];
            *(float4*)(bf)     = *(const float4*)&Bs[kk][tx*8];
            *(float4*)(bf + 4) = *(const float4*)&Bs[kk][tx*8 + 4];
#pragma unroll
            for (int i = 0; i < 8; i++)
#pragma unroll
                for (int j = 0; j < 8; j++)
                    acc[i][j] = fmaf(af[i], bf[j], acc[i][j]);
        }
        __syncthreads();
    }

    float bias[8];
#pragma unroll
    for (int j = 0; j < 8; j++) {
        int n = n0 + tx*8 + j;
        bias[j] = (n < 1536) ? (bif[n] + bhf[n]) : (bib[n - 1536] + bhb[n - 1536]);
    }
#pragma unroll
    for (int i = 0; i < 8; i++) {
        size_t row = (size_t)(m0 + ty*8 + i) * 3072 + (size_t)(n0 + tx*8);
        float4 v0, v1;
        v0.x = acc[i][0] + bias[0]; v0.y = acc[i][1] + bias[1];
        v0.z = acc[i][2] + bias[2]; v0.w = acc[i][3] + bias[3];
        v1.x = acc[i][4] + bias[4]; v1.y = acc[i][5] + bias[5];
        v1.z = acc[i][6] + bias[6]; v1.w = acc[i][7] + bias[7];
        *(float4*)&g_pre[row]     = v0;
        *(float4*)&g_pre[row + 4] = v1;
    }
}

// ---------------------------------------------------------------------------
// Kernel 2: persistent BiLSTM recurrence.
// Grid = 128 blocks (dir[2] x kgroup[16] x bgroup[4]), 128 threads, 1 block/SM.
// Block owns k-slice [k0,k0+24) for 16 batches: computes all 4 gate rows for
// its slice, updates c (block-private smem) and h (global, barrier-exchanged).
// W_hh slice cached in smem for all 512 steps.
// ---------------------------------------------------------------------------
__device__ __forceinline__ float sigf(float x) { return 1.f / (1.f + expf(-x)); }

#define REC_SMEM_FLOATS (96*388 + 384*16 + 96*17 + 384)

__device__ __forceinline__ void fma_row(float acc[4], float4 w,
                                        float4 ha, float4 hb, float4 hc, float4 hd)
{
    acc[0] = fmaf(w.w, hd.x, fmaf(w.z, hc.x, fmaf(w.y, hb.x, fmaf(w.x, ha.x, acc[0]))));
    acc[1] = fmaf(w.w, hd.y, fmaf(w.z, hc.y, fmaf(w.y, hb.y, fmaf(w.x, ha.y, acc[1]))));
    acc[2] = fmaf(w.w, hd.z, fmaf(w.z, hc.z, fmaf(w.y, hb.z, fmaf(w.x, ha.z, acc[2]))));
    acc[3] = fmaf(w.w, hd.w, fmaf(w.z, hc.w, fmaf(w.y, hb.w, fmaf(w.x, ha.w, acc[3]))));
}

__global__ __launch_bounds__(128) void k_rec(
    const float* __restrict__ whf, const float* __restrict__ whb,
    const float* __restrict__ h0, const float* __restrict__ c0)
{
    extern __shared__ float sm[];
    float* w_s    = sm;                       // [96][388] padded (conflict-free)
    float* h_s    = sm + 96*388;              // [384][16]  h_prev[k][b]
    float* gate_s = h_s + 384*16;             // [96][17]
    float* c_s    = gate_s + 96*17;           // [24*16]

    const int bid = blockIdx.x;
    const int dir = bid >> 6;
    const int kg  = (bid >> 2) & 15;
    const int bg  = bid & 3;
    const int k0  = kg * 24, b0 = bg * 16;
    const int tid = threadIdx.x;
    const float* whh = dir ? whb : whf;

    // Load W_hh slice: rows r=0..95 -> global row gate*384 + k0 + kk
    for (int idx = tid; idx < 96*96; idx += 128) {
        int r = idx / 96, cq = (idx - r*96) * 4;
        int gate = r / 24, kk = r - gate*24;
        float4 v = *(const float4*)(whh + (size_t)(gate*384 + k0 + kk) * 384 + cq);
        *(float4*)&w_s[r*388 + cq] = v;
    }
    // Load c0 slice
    for (int idx = tid; idx < 384; idx += 128) {
        int kk = idx >> 4, b = idx & 15;
        c_s[idx] = c0[((size_t)dir*64 + b0 + b) * 384 + k0 + kk];
    }
    __syncthreads();

    const int rg = tid >> 2;   // 0..31 -> rows 3rg..3rg+2
    const int bq = tid & 3;    // 0..3  -> batches 4bq..4bq+3
    const float* wr0 = w_s + (3*rg + 0) * 388;
    const float* wr1 = w_s + (3*rg + 1) * 388;
    const float* wr2 = w_s + (3*rg + 2) * 388;
    int grow[3];
#pragma unroll
    for (int i = 0; i < 3; i++) {
        int r = 3*rg + i;
        grow[i] = dir*1536 + (r/24)*384 + k0 + (r - (r/24)*24);
    }
    volatile unsigned int* bar = &g_bar[dir*4 + bg];

    for (int s = 0; s < 512; s++) {
        const int t = dir ? (511 - s) : s;

        // fill h_prev into smem (all 384 k for our 16 batches)
        if (s == 0) {
            for (int idx = tid; idx < 384*16; idx += 128) {
                int k = idx >> 4, b = idx & 15;
                h_s[idx] = h0[((size_t)dir*64 + b0 + b) * 384 + k];
            }
        } else {
            const int tp = dir ? (t + 1) : (t - 1);
            const float* hp = &g_h[dir][tp][0][b0];
            for (int idx = tid; idx < 384*4; idx += 128) {
                int k = idx >> 2, q = idx & 3;
                float4 v = *(const float4*)(hp + (size_t)k*64 + q*4);
                *(float4*)&h_s[k*16 + q*4] = v;
            }
        }
        __syncthreads();

        // init accumulators with precomputed x-projection + biases
        float acc[3][4];
#pragma unroll
        for (int i = 0; i < 3; i++)
#pragma unroll
            for (int j = 0; j < 4; j++)
                acc[i][j] = g_pre[((size_t)t*64 + b0 + 4*bq + j) * 3072 + grow[i]];

        // dot over k (h @ W_hh^T)
#pragma unroll 2
        for (int k = 0; k < 384; k += 4) {
            float4 w0 = *(const float4*)(wr0 + k);
            float4 w1 = *(const float4*)(wr1 + k);
            float4 w2 = *(const float4*)(wr2 + k);
            float4 ha = *(const float4*)&h_s[(k+0)*16 + bq*4];
            float4 hb = *(const float4*)&h_s[(k+1)*16 + bq*4];
            float4 hc = *(const float4*)&h_s[(k+2)*16 + bq*4];
            float4 hd = *(const float4*)&h_s[(k+3)*16 + bq*4];
            fma_row(acc[0], w0, ha, hb, hc, hd);
            fma_row(acc[1], w1, ha, hb, hc, hd);
            fma_row(acc[2], w2, ha, hb, hc, hd);
        }
#pragma unroll
        for (int i = 0; i < 3; i++)
#pragma unroll
            for (int j = 0; j < 4; j++)
                gate_s[(3*rg + i)*17 + 4*bq + j] = acc[i][j];
        __syncthreads();

        // elementwise LSTM cell update (gate order i,f,g,o)
        for (int idx = tid; idx < 384; idx += 128) {
            int kk = idx >> 4, b = idx & 15;
            float gi = gate_s[(kk     )*17 + b];
            float gf = gate_s[(kk + 24)*17 + b];
            float gg = gate_s[(kk + 48)*17 + b];
            float go = gate_s[(kk + 72)*17 + b];
            float c = sigf(gf) * c_s[idx] + sigf(gi) * tanhf(gg);
            c_s[idx] = c;
            g_h[dir][t][k0 + kk][b0 + b] = sigf(go) * tanhf(c);
        }
        __threadfence();
        __syncthreads();

        // 16-block barrier for this (dir, batch-group)
        if (tid == 0) {
            atomicAdd((unsigned int*)&g_bar[dir*4 + bg], 1u);
            const unsigned int target = 16u * (unsigned)(s + 1);
            while (*bar < target) { }
            __threadfence();
        }
        __syncthreads();
    }
}

// ---------------------------------------------------------------------------
// Kernel 3: emissions  feats[t][b][l] = concat(hf,hb) . fc_w[l] + fc_b[l]
// ---------------------------------------------------------------------------
__global__ __launch_bounds__(256) void k_fc(const float* __restrict__ fcw,
                                            const float* __restrict__ fcb)
{
    __shared__ float wsh[12*768];
    __shared__ float bsh[12];
    const int t = blockIdx.x;
    const int tid = threadIdx.x;
    for (int i = tid; i < 12*768; i += 256) wsh[i] = fcw[i];
    if (tid < 12) bsh[tid] = fcb[tid];
    __syncthreads();

    for (int o = tid; o < 768; o += 256) {
        int l = o >> 6, b = o & 63;
        const float* wl = &wsh[l*768];
        float s = bsh[l];
#pragma unroll 4
        for (int k = 0; k < 384; k++) s = fmaf(g_h[0][t][k][b], wl[k], s);
#pragma unroll 4
        for (int k = 0; k < 384; k++) s = fmaf(g_h[1][t][k][b], wl[384 + k], s);
        g_feat[t][b][l] = s;
    }
}

// ---------------------------------------------------------------------------
// Kernel 4: Viterbi forward + backtrace. 1 block, 768 threads (b,l) pairs.
// Matches JAX: init fv = NEG except fv[start]=0 (feats[t=0] unused);
// argmax ties -> first index (strict > ascending scan).
// ---------------------------------------------------------------------------
__global__ __launch_bounds__(768) void k_vit(const float* __restrict__ trans,
                                             const int* __restrict__ start_idx,
                                             float* __restrict__ out)
{
    __shared__ float fvbuf[2][64][12];
    __shared__ float tr[12][12];
    const int tid = threadIdx.x;
    const int b = tid / 12, l = tid - b*12;

    if (tid < 144) tr[tid / 12][tid % 12] = trans[tid];
    const int s0 = *start_idx;
    fvbuf[0][b][l] = (l == s0) ? 0.f : NEGV;
    __syncthreads();

    float ft_next = g_feat[1][b][l];
    for (int t = 1; t < 512; t++) {
        const float* fv = fvbuf[(t - 1) & 1][b];
        float ft = ft_next;
        if (t < 511) ft_next = g_feat[t + 1][b][l];
        float best = tr[l][0] + fv[0];
        int arg = 0;
#pragma unroll
        for (int p = 1; p < 12; p++) {
            float sc = tr[l][p] + fv[p];
            if (sc > best) { best = sc; arg = p; }
        }
        fvbuf[t & 1][b][l] = best + ft;
        g_ptr[t - 1][b][l] = (unsigned char)arg;
        __syncthreads();
    }

    // backtrace (final fv is in buffer parity 511&1 = 1)
    if (tid < 64) {
        const int bb = tid;
        float best = fvbuf[1][bb][0];
        int last = 0;
#pragma unroll
        for (int p = 1; p < 12; p++)
            if (fvbuf[1][bb][p] > best) { best = fvbuf[1][bb][p]; last = p; }
        out[bb] = best;
        float* path = out + 64 + (size_t)bb * 512;
        int cur = last;
        path[511] = (float)cur;
        for (int t = 510; t >= 0; t--) {
            cur = g_ptr[t][bb][cur];
            path[t] = (float)cur;
        }
    }
}

// ---------------------------------------------------------------------------
extern "C" void kernel_launch(void* const* d_in, const int* in_sizes, int n_in,
                              void* d_out, int out_size)
{
    const float* hs   = (const float*)d_in[0];
    const float* h0   = (const float*)d_in[1];
    const float* c0   = (const float*)d_in[2];
    const float* wihf = (const float*)d_in[3];
    const float* whhf = (const float*)d_in[4];
    const float* bihf = (const float*)d_in[5];
    const float* bhhf = (const float*)d_in[6];
    const float* wihb = (const float*)d_in[7];
    const float* whhb = (const float*)d_in[8];
    const float* bihb = (const float*)d_in[9];
    const float* bhhb = (const float*)d_in[10];
    const float* fcw  = (const float*)d_in[11];
    const float* fcb  = (const float*)d_in[12];
    const float* trans= (const float*)d_in[13];
    const int*   stp  = (const int*)d_in[14];
    (void)in_sizes; (void)n_in; (void)out_size;

    const size_t rec_smem = (size_t)REC_SMEM_FLOATS * sizeof(float); // 181,632 B
    cudaFuncSetAttribute(k_rec, cudaFuncAttributeMaxDynamicSharedMemorySize,
                         (int)rec_smem);

    k_init<<<1, 32>>>();

    dim3 gg(24, 256);   // N tiles fastest (A-tile reuse in L2)
    k_gemm<<<gg, 256>>>(hs, wihf, wihb, bihf, bhhf, bihb, bhhb);

    k_rec<<<128, 128, rec_smem>>>(whhf, whhb, h0, c0);

    k_fc<<<512, 256>>>(fcw, fcb);

    k_vit<<<1, 768>>>(trans, stp, (float*)d_out);
}

// round 6
// speedup vs baseline: 1.0088x; 1.0088x over previous
#include <cuda_runtime.h>
#include <cstdint>
#include <cstddef>

// ---------------------------------------------------------------------------
// BertBiLstmCrf: BiLSTM(768->2x384) -> FC(768->12) -> Viterbi decode
// B=64, T=512, H=768, LH=384, L=12
// Output: [score(64) ; path(64*512)] as float32
// ---------------------------------------------------------------------------

#define NEGV (-1000.0f)

__device__ float        g_pre[(size_t)32768 * 3072];   // gate pre-acts [t*64+b][dir*1536+row]
__device__ float        g_h[2][512][384][64];          // [dir][t][k][b]
__device__ float        g_feat[512][64][12];
__device__ unsigned char g_ptr[511][64][12];
__device__ unsigned int g_bar[8];

__global__ void k_init() {
    if (threadIdx.x < 8) g_bar[threadIdx.x] = 0u;
}

// ---------------------------------------------------------------------------
// Kernel 1: input-projection GEMM via 3xTF32 mma.sync (error-compensated).
// C[m][n] = sum_k A[m][k]*W[n][k] + bias[n]; m=t*64+b (A row = hs[b][t]),
// n<1536 forward weights, else backward. M=32768, N=3072, K=768.
// CTA 128x128, BK=32, 256 thr, 8 warps (4x2), warp tile 32x64.
// smem holds (hi,lo) tf32 pairs in fragment order: all LDS are LDS.128,
// lane-contiguous, conflict-free. Double-buffered.
// ---------------------------------------------------------------------------
__device__ __forceinline__ unsigned f2tf(float x) {
    unsigned r; asm("cvt.rna.tf32.f32 %0, %1;" : "=r"(r) : "f"(x)); return r;
}
__device__ __forceinline__ void mma_tf32(float c[4],
    unsigned a0, unsigned a1, unsigned a2, unsigned a3,
    unsigned b0, unsigned b1)
{
    asm volatile(
      "mma.sync.aligned.m16n8k8.row.col.f32.tf32.tf32.f32 "
      "{%0,%1,%2,%3},{%4,%5,%6,%7},{%8,%9},{%0,%1,%2,%3};"
      : "+f"(c[0]), "+f"(c[1]), "+f"(c[2]), "+f"(c[3])
      : "r"(a0), "r"(a1), "r"(a2), "r"(a3), "r"(b0), "r"(b1));
}

// Split 16 loaded floats (one row-half of a tile) into fragment-order chunks:
// chunk float4 = (hi(k=c), lo(k=c), hi(k=c+4), lo(k=c+4)); c = 0..3,
// two k8 sub-blocks (j2) per 16-float half.
__device__ __forceinline__ void split_store(float4* dst, const float4 r[4],
                                            int slot_j0, int slot_j1)
{
    const float* f = (const float*)r;
#pragma unroll
    for (int j2 = 0; j2 < 2; j2++) {
        int base = j2 ? slot_j1 : slot_j0;
#pragma unroll
        for (int c = 0; c < 4; c++) {
            float x0 = f[j2*8 + c];
            float x1 = f[j2*8 + c + 4];
            unsigned h0 = f2tf(x0); float l0 = x0 - __uint_as_float(h0);
            unsigned h1 = f2tf(x1); float l1 = x1 - __uint_as_float(h1);
            float4 v;
            v.x = __uint_as_float(h0); v.y = __uint_as_float(f2tf(l0));
            v.z = __uint_as_float(h1); v.w = __uint_as_float(f2tf(l1));
            dst[base + c] = v;
        }
    }
}

__global__ __launch_bounds__(256) void k_gemm(
    const float* __restrict__ hs,
    const float* __restrict__ wf, const float* __restrict__ wb,
    const float* __restrict__ bif, const float* __restrict__ bhf,
    const float* __restrict__ bib, const float* __restrict__ bhb)
{
    extern __shared__ float4 gsm[];
    // gsm layout (float4 units): A buf0 [0,2048), A buf1 [2048,4096),
    //                            B buf0 [4096,6144), B buf1 [6144,8192)
    const int tid  = threadIdx.x;
    const int lane = tid & 31;
    const int wid  = tid >> 5;
    const int wm   = wid & 3;       // 4 warp-m groups (32 rows each)
    const int wn   = wid >> 2;      // 2 warp-n groups (64 cols each)
    const int m0 = blockIdx.y * 128;
    const int n0 = blockIdx.x * 128;

    // ---- loader mapping: thread = (row = tid>>1, k-half = tid&1) ----
    const int lrow = tid >> 1;
    const int lh   = tid & 1;
    const int mA   = m0 + lrow;
    const float* agp = hs + ((size_t)(mA & 63) * 512 + (mA >> 6)) * 768 + lh*16;
    const int   nB   = n0 + lrow;
    const float* bgp = ((n0 < 1536) ? (wf + (size_t)nB * 768)
                                    : (wb + (size_t)(nB - 1536) * 768)) + lh*16;

    // A store slots: chunk index = ((awm*4 + k8)*4 + sub)*32 + alr*4 + c
    const int awm  = lrow >> 5;
    const int amw  = lrow & 31;
    const int asub = (amw >> 4) * 2 + ((amw >> 3) & 1);
    const int alr  = amw & 7;
    const int aslot0 = ((awm*4 + lh*2 + 0)*4 + asub)*32 + alr*4;
    const int aslot1 = ((awm*4 + lh*2 + 1)*4 + asub)*32 + alr*4;
    // B store slots: ((bwn*4 + k8)*8 + bna)*32 + bnn*4 + c
    const int bwn = lrow >> 6;
    const int bnwl = lrow & 63;
    const int bna = bnwl >> 3;
    const int bnn = bnwl & 7;
    const int bslot0 = ((bwn*4 + lh*2 + 0)*8 + bna)*32 + bnn*4;
    const int bslot1 = ((bwn*4 + lh*2 + 1)*8 + bna)*32 + bnn*4;

    float cacc[2][8][4];
#pragma unroll
    for (int am = 0; am < 2; am++)
#pragma unroll
        for (int na = 0; na < 8; na++)
#pragma unroll
            for (int q = 0; q < 4; q++) cacc[am][na][q] = 0.f;

    float4 aR[4], bR[4];
    // prologue: tile 0
#pragma unroll
    for (int j = 0; j < 4; j++) {
        aR[j] = *(const float4*)(agp + j*4);
        bR[j] = *(const float4*)(bgp + j*4);
    }
    split_store(gsm,        aR, aslot0, aslot1);
    split_store(gsm + 4096, bR, bslot0, bslot1);
    __syncthreads();

    int buf = 0;
    for (int kt = 0; kt < 24; kt++) {
        const bool more = (kt + 1) < 24;
        if (more) {
            const int k0 = (kt + 1) * 32;
#pragma unroll
            for (int j = 0; j < 4; j++) {
                aR[j] = *(const float4*)(agp + k0 + j*4);
                bR[j] = *(const float4*)(bgp + k0 + j*4);
            }
        }
        const float4* Ab = gsm + buf*2048;
        const float4* Bb = gsm + 4096 + buf*2048;
#pragma unroll
        for (int k8 = 0; k8 < 4; k8++) {
            unsigned ah[2][4], al[2][4];
#pragma unroll
            for (int am = 0; am < 2; am++) {
                float4 c0 = Ab[((wm*4 + k8)*4 + am*2 + 0)*32 + lane]; // a0/a2
                float4 c1 = Ab[((wm*4 + k8)*4 + am*2 + 1)*32 + lane]; // a1/a3
                ah[am][0] = __float_as_uint(c0.x); al[am][0] = __float_as_uint(c0.y);
                ah[am][2] = __float_as_uint(c0.z); al[am][2] = __float_as_uint(c0.w);
                ah[am][1] = __float_as_uint(c1.x); al[am][1] = __float_as_uint(c1.y);
                ah[am][3] = __float_as_uint(c1.z); al[am][3] = __float_as_uint(c1.w);
            }
#pragma unroll
            for (int na = 0; na < 8; na++) {
                float4 bb = Bb[((wn*4 + k8)*8 + na)*32 + lane];
                unsigned bh0 = __float_as_uint(bb.x), bl0 = __float_as_uint(bb.y);
                unsigned bh1 = __float_as_uint(bb.z), bl1 = __float_as_uint(bb.w);
#pragma unroll
                for (int am = 0; am < 2; am++) {
                    mma_tf32(cacc[am][na], ah[am][0], ah[am][1], ah[am][2], ah[am][3], bl0, bl1);
                    mma_tf32(cacc[am][na], al[am][0], al[am][1], al[am][2], al[am][3], bh0, bh1);
                    mma_tf32(cacc[am][na], ah[am][0], ah[am][1], ah[am][2], ah[am][3], bh0, bh1);
                }
            }
        }
        if (more) {
            split_store(gsm + (buf^1)*2048,        aR, aslot0, aslot1);
            split_store(gsm + 4096 + (buf^1)*2048, bR, bslot0, bslot1);
        }
        __syncthreads();
        buf ^= 1;
    }

    // epilogue: + bias, store to g_pre
    const int fwd = (n0 < 1536);
    const float* bi = fwd ? bif : bib;
    const float* bh = fwd ? bhf : bhb;
    const int noff = fwd ? 0 : 1536;
#pragma unroll
    for (int na = 0; na < 8; na++) {
        const int ngl = n0 + wn*64 + na*8 + (lane & 3)*2;
        const int nl  = ngl - noff;
        const float bx = bi[nl] + bh[nl];
        const float by = bi[nl + 1] + bh[nl + 1];
#pragma unroll
        for (int am = 0; am < 2; am++) {
            const int r = m0 + wm*32 + am*16 + (lane >> 2);
            float2 v0; v0.x = cacc[am][na][0] + bx; v0.y = cacc[am][na][1] + by;
            float2 v1; v1.x = cacc[am][na][2] + bx; v1.y = cacc[am][na][3] + by;
            *(float2*)&g_pre[(size_t)r * 3072 + ngl]       = v0;
            *(float2*)&g_pre[(size_t)(r + 8) * 3072 + ngl] = v1;
        }
    }
}

// ---------------------------------------------------------------------------
// Kernel 2: persistent BiLSTM recurrence (fp32). 128 blocks x 128 thr.
// ---------------------------------------------------------------------------
__device__ __forceinline__ float sigf(float x) { return 1.f / (1.f + expf(-x)); }

#define REC_SMEM_FLOATS (96*388 + 384*16 + 96*17 + 384)

__device__ __forceinline__ void fma_row(float acc[4], float4 w,
                                        float4 ha, float4 hb, float4 hc, float4 hd)
{
    acc[0] = fmaf(w.w, hd.x, fmaf(w.z, hc.x, fmaf(w.y, hb.x, fmaf(w.x, ha.x, acc[0]))));
    acc[1] = fmaf(w.w, hd.y, fmaf(w.z, hc.y, fmaf(w.y, hb.y, fmaf(w.x, ha.y, acc[1]))));
    acc[2] = fmaf(w.w, hd.z, fmaf(w.z, hc.z, fmaf(w.y, hb.z, fmaf(w.x, ha.z, acc[2]))));
    acc[3] = fmaf(w.w, hd.w, fmaf(w.z, hc.w, fmaf(w.y, hb.w, fmaf(w.x, ha.w, acc[3]))));
}

__global__ __launch_bounds__(128) void k_rec(
    const float* __restrict__ whf, const float* __restrict__ whb,
    const float* __restrict__ h0, const float* __restrict__ c0)
{
    extern __shared__ float sm[];
    float* w_s    = sm;                       // [96][388]
    float* h_s    = sm + 96*388;              // [384][16]
    float* gate_s = h_s + 384*16;             // [96][17]
    float* c_s    = gate_s + 96*17;           // [24*16]

    const int bid = blockIdx.x;
    const int dir = bid >> 6;
    const int kg  = (bid >> 2) & 15;
    const int bg  = bid & 3;
    const int k0  = kg * 24, b0 = bg * 16;
    const int tid = threadIdx.x;
    const float* whh = dir ? whb : whf;

    for (int idx = tid; idx < 96*96; idx += 128) {
        int r = idx / 96, cq = (idx - r*96) * 4;
        int gate = r / 24, kk = r - gate*24;
        float4 v = *(const float4*)(whh + (size_t)(gate*384 + k0 + kk) * 384 + cq);
        *(float4*)&w_s[r*388 + cq] = v;
    }
    for (int idx = tid; idx < 384; idx += 128) {
        int kk = idx >> 4, b = idx & 15;
        c_s[idx] = c0[((size_t)dir*64 + b0 + b) * 384 + k0 + kk];
    }
    __syncthreads();

    const int rg = tid >> 2;
    const int bq = tid & 3;
    const float* wr0 = w_s + (3*rg + 0) * 388;
    const float* wr1 = w_s + (3*rg + 1) * 388;
    const float* wr2 = w_s + (3*rg + 2) * 388;
    int grow[3];
#pragma unroll
    for (int i = 0; i < 3; i++) {
        int r = 3*rg + i;
        grow[i] = dir*1536 + (r/24)*384 + k0 + (r - (r/24)*24);
    }
    volatile unsigned int* bar = &g_bar[dir*4 + bg];

    // preload gate pre-activations for the first step
    float acc[3][4];
    {
        const int t0 = dir ? 511 : 0;
#pragma unroll
        for (int i = 0; i < 3; i++)
#pragma unroll
            for (int j = 0; j < 4; j++)
                acc[i][j] = g_pre[((size_t)t0*64 + b0 + 4*bq + j) * 3072 + grow[i]];
    }

    for (int s = 0; s < 512; s++) {
        const int t = dir ? (511 - s) : s;

        if (s == 0) {
            for (int idx = tid; idx < 384*16; idx += 128) {
                int k = idx >> 4, b = idx & 15;
                h_s[idx] = h0[((size_t)dir*64 + b0 + b) * 384 + k];
            }
        } else {
            const int tp = dir ? (t + 1) : (t - 1);
            const float* hp = &g_h[dir][tp][0][b0];
            for (int idx = tid; idx < 384*4; idx += 128) {
                int k = idx >> 2, q = idx & 3;
                float4 v = *(const float4*)(hp + (size_t)k*64 + q*4);
                *(float4*)&h_s[k*16 + q*4] = v;
            }
        }
        __syncthreads();

#pragma unroll 2
        for (int k = 0; k < 384; k += 4) {
            float4 w0 = *(const float4*)(wr0 + k);
            float4 w1 = *(const float4*)(wr1 + k);
            float4 w2 = *(const float4*)(wr2 + k);
            float4 ha = *(const float4*)&h_s[(k+0)*16 + bq*4];
            float4 hb = *(const float4*)&h_s[(k+1)*16 + bq*4];
            float4 hc = *(const float4*)&h_s[(k+2)*16 + bq*4];
            float4 hd = *(const float4*)&h_s[(k+3)*16 + bq*4];
            fma_row(acc[0], w0, ha, hb, hc, hd);
            fma_row(acc[1], w1, ha, hb, hc, hd);
            fma_row(acc[2], w2, ha, hb, hc, hd);
        }
#pragma unroll
        for (int i = 0; i < 3; i++)
#pragma unroll
            for (int j = 0; j < 4; j++)
                gate_s[(3*rg + i)*17 + 4*bq + j] = acc[i][j];
        __syncthreads();

        for (int idx = tid; idx < 384; idx += 128) {
            int kk = idx >> 4, b = idx & 15;
            float gi = gate_s[(kk     )*17 + b];
            float gf = gate_s[(kk + 24)*17 + b];
            float gg = gate_s[(kk + 48)*17 + b];
            float go = gate_s[(kk + 72)*17 + b];
            float c = sigf(gf) * c_s[idx] + sigf(gi) * tanhf(gg);
            c_s[idx] = c;
            g_h[dir][t][k0 + kk][b0 + b] = sigf(go) * tanhf(c);
        }
        __threadfence();
        __syncthreads();

        if (tid == 0) atomicAdd((unsigned int*)&g_bar[dir*4 + bg], 1u);

        // hide next step's g_pre latency behind the barrier
        if (s + 1 < 512) {
            const int tn = dir ? (510 - s) : (s + 1);
#pragma unroll
            for (int i = 0; i < 3; i++)
#pragma unroll
                for (int j = 0; j < 4; j++)
                    acc[i][j] = g_pre[((size_t)tn*64 + b0 + 4*bq + j) * 3072 + grow[i]];
        }

        if (tid == 0) {
            const unsigned int target = 16u * (unsigned)(s + 1);
            while (*bar < target) { }
            __threadfence();
        }
        __syncthreads();
    }
}

// ---------------------------------------------------------------------------
// Kernel 3: emissions (4 independent accumulator chains for MLP)
// ---------------------------------------------------------------------------
__global__ __launch_bounds__(256) void k_fc(const float* __restrict__ fcw,
                                            const float* __restrict__ fcb)
{
    __shared__ float wsh[12*768];
    __shared__ float bsh[12];
    const int t = blockIdx.x;
    const int tid = threadIdx.x;
    for (int i = tid; i < 12*768; i += 256) wsh[i] = fcw[i];
    if (tid < 12) bsh[tid] = fcb[tid];
    __syncthreads();

    for (int o = tid; o < 768; o += 256) {
        int l = o >> 6, b = o & 63;
        const float* wl  = &wsh[l*768];
        const float* hp0 = &g_h[0][t][0][b];
        const float* hp1 = &g_h[1][t][0][b];
        float s0 = 0.f, s1 = 0.f, s2 = 0.f, s3 = 0.f;
#pragma unroll 4
        for (int k = 0; k < 384; k += 4) {
            s0 = fmaf(hp0[(size_t)(k+0)*64], wl[k+0], s0);
            s1 = fmaf(hp0[(size_t)(k+1)*64], wl[k+1], s1);
            s2 = fmaf(hp0[(size_t)(k+2)*64], wl[k+2], s2);
            s3 = fmaf(hp0[(size_t)(k+3)*64], wl[k+3], s3);
        }
#pragma unroll 4
        for (int k = 0; k < 384; k += 4) {
            s0 = fmaf(hp1[(size_t)(k+0)*64], wl[384+k+0], s0);
            s1 = fmaf(hp1[(size_t)(k+1)*64], wl[384+k+1], s1);
            s2 = fmaf(hp1[(size_t)(k+2)*64], wl[384+k+2], s2);
            s3 = fmaf(hp1[(size_t)(k+3)*64], wl[384+k+3], s3);
        }
        g_feat[t][b][l] = bsh[l] + ((s0 + s1) + (s2 + s3));
    }
}

// ---------------------------------------------------------------------------
// Kernel 4: Viterbi forward + backtrace (1 block, 768 threads)
// ---------------------------------------------------------------------------
__global__ __launch_bounds__(768) void k_vit(const float* __restrict__ trans,
                                             const int* __restrict__ start_idx,
                                             float* __restrict__ out)
{
    __shared__ float fvbuf[2][64][12];
    __shared__ float tr[12][12];
    const int tid = threadIdx.x;
    const int b = tid / 12, l = tid - b*12;

    if (tid < 144) tr[tid / 12][tid % 12] = trans[tid];
    const int s0 = *start_idx;
    fvbuf[0][b][l] = (l == s0) ? 0.f : NEGV;
    __syncthreads();

    float ft_next = g_feat[1][b][l];
    for (int t = 1; t < 512; t++) {
        const float* fv = fvbuf[(t - 1) & 1][b];
        float ft = ft_next;
        if (t < 511) ft_next = g_feat[t + 1][b][l];
        float best = tr[l][0] + fv[0];
        int arg = 0;
#pragma unroll
        for (int p = 1; p < 12; p++) {
            float sc = tr[l][p] + fv[p];
            if (sc > best) { best = sc; arg = p; }
        }
        fvbuf[t & 1][b][l] = best + ft;
        g_ptr[t - 1][b][l] = (unsigned char)arg;
        __syncthreads();
    }

    if (tid < 64) {
        const int bb = tid;
        float best = fvbuf[1][bb][0];
        int last = 0;
#pragma unroll
        for (int p = 1; p < 12; p++)
            if (fvbuf[1][bb][p] > best) { best = fvbuf[1][bb][p]; last = p; }
        out[bb] = best;
        float* path = out + 64 + (size_t)bb * 512;
        int cur = last;
        path[511] = (float)cur;
        for (int t = 510; t >= 0; t--) {
            cur = g_ptr[t][bb][cur];
            path[t] = (float)cur;
        }
    }
}

// ---------------------------------------------------------------------------
extern "C" void kernel_launch(void* const* d_in, const int* in_sizes, int n_in,
                              void* d_out, int out_size)
{
    const float* hs   = (const float*)d_in[0];
    const float* h0   = (const float*)d_in[1];
    const float* c0   = (const float*)d_in[2];
    const float* wihf = (const float*)d_in[3];
    const float* whhf = (const float*)d_in[4];
    const float* bihf = (const float*)d_in[5];
    const float* bhhf = (const float*)d_in[6];
    const float* wihb = (const float*)d_in[7];
    const float* whhb = (const float*)d_in[8];
    const float* bihb = (const float*)d_in[9];
    const float* bhhb = (const float*)d_in[10];
    const float* fcw  = (const float*)d_in[11];
    const float* fcb  = (const float*)d_in[12];
    const float* trans= (const float*)d_in[13];
    const int*   stp  = (const int*)d_in[14];
    (void)in_sizes; (void)n_in; (void)out_size;

    static int attr_set = 0;
    const size_t rec_smem  = (size_t)REC_SMEM_FLOATS * sizeof(float); // 181,632 B
    const size_t gemm_smem = 8192 * sizeof(float4);                   // 131,072 B
    cudaFuncSetAttribute(k_rec,  cudaFuncAttributeMaxDynamicSharedMemorySize, (int)rec_smem);
    cudaFuncSetAttribute(k_gemm, cudaFuncAttributeMaxDynamicSharedMemorySize, (int)gemm_smem);
    (void)attr_set;

    k_init<<<1, 32>>>();

    dim3 gg(24, 256);
    k_gemm<<<gg, 256, gemm_smem>>>(hs, wihf, wihb, bihf, bhhf, bihb, bhhb);

    k_rec<<<128, 128, rec_smem>>>(whhf, whhb, h0, c0);

    k_fc<<<512, 256>>>(fcw, fcb);

    k_vit<<<1, 768>>>(trans, stp, (float*)d_out);
}

// round 7
// speedup vs baseline: 1.0099x; 1.0010x over previous
#include <cuda_runtime.h>
#include <cstdint>
#include <cstddef>

// ---------------------------------------------------------------------------
// BertBiLstmCrf: BiLSTM(768->2x384) -> FC(768->12) -> Viterbi decode
// B=64, T=512, H=768, LH=384, L=12
// Output: [score(64) ; path(64*512)] as float32
// ---------------------------------------------------------------------------

#define NEGV (-1000.0f)

__device__ float        g_pre[(size_t)32768 * 3072];   // gate pre-acts [t*64+b][dir*1536+row]
__device__ float        g_h[2][512][384][64];          // [dir][t][k][b]
__device__ float        g_feat[512][64][12];
__device__ unsigned char g_ptr[511][64][12];
__device__ unsigned int g_bar[8];

__global__ void k_init() {
    if (threadIdx.x < 8) g_bar[threadIdx.x] = 0u;
}

// ---------------------------------------------------------------------------
// Kernel 1: input-projection GEMM via 3xTF32 mma.sync (error-compensated).
// C[m][n] = sum_k A[m][k]*W[n][k] + bias[n]; m=t*64+b (A row = hs[b][t]),
// n<1536 forward weights, else backward. M=32768, N=3072, K=768.
// CTA 128x128, BK=32, 256 thr, 8 warps (4x2), warp tile 32x64.
// smem holds (hi,lo) tf32 pairs in fragment order: all LDS are LDS.128,
// lane-contiguous, conflict-free. Double-buffered.
// ---------------------------------------------------------------------------
__device__ __forceinline__ unsigned f2tf(float x) {
    unsigned r; asm("cvt.rna.tf32.f32 %0, %1;" : "=r"(r) : "f"(x)); return r;
}
__device__ __forceinline__ void mma_tf32(float c[4],
    unsigned a0, unsigned a1, unsigned a2, unsigned a3,
    unsigned b0, unsigned b1)
{
    asm volatile(
      "mma.sync.aligned.m16n8k8.row.col.f32.tf32.tf32.f32 "
      "{%0,%1,%2,%3},{%4,%5,%6,%7},{%8,%9},{%0,%1,%2,%3};"
      : "+f"(c[0]), "+f"(c[1]), "+f"(c[2]), "+f"(c[3])
      : "r"(a0), "r"(a1), "r"(a2), "r"(a3), "r"(b0), "r"(b1));
}

// Split 16 loaded floats (one row-half of a tile) into fragment-order chunks:
// chunk float4 = (hi(k=c), lo(k=c), hi(k=c+4), lo(k=c+4)); c = 0..3,
// two k8 sub-blocks (j2) per 16-float half.
__device__ __forceinline__ void split_store(float4* dst, const float4 r[4],
                                            int slot_j0, int slot_j1)
{
    const float* f = (const float*)r;
#pragma unroll
    for (int j2 = 0; j2 < 2; j2++) {
        int base = j2 ? slot_j1 : slot_j0;
#pragma unroll
        for (int c = 0; c < 4; c++) {
            float x0 = f[j2*8 + c];
            float x1 = f[j2*8 + c + 4];
            unsigned h0 = f2tf(x0); float l0 = x0 - __uint_as_float(h0);
            unsigned h1 = f2tf(x1); float l1 = x1 - __uint_as_float(h1);
            float4 v;
            v.x = __uint_as_float(h0); v.y = __uint_as_float(f2tf(l0));
            v.z = __uint_as_float(h1); v.w = __uint_as_float(f2tf(l1));
            dst[base + c] = v;
        }
    }
}

__global__ __launch_bounds__(256) void k_gemm(
    const float* __restrict__ hs,
    const float* __restrict__ wf, const float* __restrict__ wb,
    const float* __restrict__ bif, const float* __restrict__ bhf,
    const float* __restrict__ bib, const float* __restrict__ bhb)
{
    extern __shared__ float4 gsm[];
    // gsm layout (float4 units): A buf0 [0,2048), A buf1 [2048,4096),
    //                            B buf0 [4096,6144), B buf1 [6144,8192)
    const int tid  = threadIdx.x;
    const int lane = tid & 31;
    const int wid  = tid >> 5;
    const int wm   = wid & 3;       // 4 warp-m groups (32 rows each)
    const int wn   = wid >> 2;      // 2 warp-n groups (64 cols each)
    const int m0 = blockIdx.y * 128;
    const int n0 = blockIdx.x * 128;

    // ---- loader mapping: thread = (row = tid>>1, k-half = tid&1) ----
    const int lrow = tid >> 1;
    const int lh   = tid & 1;
    const int mA   = m0 + lrow;
    const float* agp = hs + ((size_t)(mA & 63) * 512 + (mA >> 6)) * 768 + lh*16;
    const int   nB   = n0 + lrow;
    const float* bgp = ((n0 < 1536) ? (wf + (size_t)nB * 768)
                                    : (wb + (size_t)(nB - 1536) * 768)) + lh*16;

    // A store slots: chunk index = ((awm*4 + k8)*4 + sub)*32 + alr*4 + c
    const int awm  = lrow >> 5;
    const int amw  = lrow & 31;
    const int asub = (amw >> 4) * 2 + ((amw >> 3) & 1);
    const int alr  = amw & 7;
    const int aslot0 = ((awm*4 + lh*2 + 0)*4 + asub)*32 + alr*4;
    const int aslot1 = ((awm*4 + lh*2 + 1)*4 + asub)*32 + alr*4;
    // B store slots: ((bwn*4 + k8)*8 + bna)*32 + bnn*4 + c
    const int bwn = lrow >> 6;
    const int bnwl = lrow & 63;
    const int bna = bnwl >> 3;
    const int bnn = bnwl & 7;
    const int bslot0 = ((bwn*4 + lh*2 + 0)*8 + bna)*32 + bnn*4;
    const int bslot1 = ((bwn*4 + lh*2 + 1)*8 + bna)*32 + bnn*4;

    float cacc[2][8][4];
#pragma unroll
    for (int am = 0; am < 2; am++)
#pragma unroll
        for (int na = 0; na < 8; na++)
#pragma unroll
            for (int q = 0; q < 4; q++) cacc[am][na][q] = 0.f;

    float4 aR[4], bR[4];
    // prologue: tile 0
#pragma unroll
    for (int j = 0; j < 4; j++) {
        aR[j] = *(const float4*)(agp + j*4);
        bR[j] = *(const float4*)(bgp + j*4);
    }
    split_store(gsm,        aR, aslot0, aslot1);
    split_store(gsm + 4096, bR, bslot0, bslot1);
    __syncthreads();

    int buf = 0;
    for (int kt = 0; kt < 24; kt++) {
        const bool more = (kt + 1) < 24;
        if (more) {
            const int k0 = (kt + 1) * 32;
#pragma unroll
            for (int j = 0; j < 4; j++) {
                aR[j] = *(const float4*)(agp + k0 + j*4);
                bR[j] = *(const float4*)(bgp + k0 + j*4);
            }
        }
        const float4* Ab = gsm + buf*2048;
        const float4* Bb = gsm + 4096 + buf*2048;
#pragma unroll
        for (int k8 = 0; k8 < 4; k8++) {
            unsigned ah[2][4], al[2][4];
#pragma unroll
            for (int am = 0; am < 2; am++) {
                float4 c0 = Ab[((wm*4 + k8)*4 + am*2 + 0)*32 + lane]; // a0/a2
                float4 c1 = Ab[((wm*4 + k8)*4 + am*2 + 1)*32 + lane]; // a1/a3
                ah[am][0] = __float_as_uint(c0.x); al[am][0] = __float_as_uint(c0.y);
                ah[am][2] = __float_as_uint(c0.z); al[am][2] = __float_as_uint(c0.w);
                ah[am][1] = __float_as_uint(c1.x); al[am][1] = __float_as_uint(c1.y);
                ah[am][3] = __float_as_uint(c1.z); al[am][3] = __float_as_uint(c1.w);
            }
#pragma unroll
            for (int na = 0; na < 8; na++) {
                float4 bb = Bb[((wn*4 + k8)*8 + na)*32 + lane];
                unsigned bh0 = __float_as_uint(bb.x), bl0 = __float_as_uint(bb.y);
                unsigned bh1 = __float_as_uint(bb.z), bl1 = __float_as_uint(bb.w);
#pragma unroll
                for (int am = 0; am < 2; am++) {
                    mma_tf32(cacc[am][na], ah[am][0], ah[am][1], ah[am][2], ah[am][3], bl0, bl1);
                    mma_tf32(cacc[am][na], al[am][0], al[am][1], al[am][2], al[am][3], bh0, bh1);
                    mma_tf32(cacc[am][na], ah[am][0], ah[am][1], ah[am][2], ah[am][3], bh0, bh1);
                }
            }
        }
        if (more) {
            split_store(gsm + (buf^1)*2048,        aR, aslot0, aslot1);
            split_store(gsm + 4096 + (buf^1)*2048, bR, bslot0, bslot1);
        }
        __syncthreads();
        buf ^= 1;
    }

    // epilogue: + bias, store to g_pre
    const int fwd = (n0 < 1536);
    const float* bi = fwd ? bif : bib;
    const float* bh = fwd ? bhf : bhb;
    const int noff = fwd ? 0 : 1536;
#pragma unroll
    for (int na = 0; na < 8; na++) {
        const int ngl = n0 + wn*64 + na*8 + (lane & 3)*2;
        const int nl  = ngl - noff;
        const float bx = bi[nl] + bh[nl];
        const float by = bi[nl + 1] + bh[nl + 1];
#pragma unroll
        for (int am = 0; am < 2; am++) {
            const int r = m0 + wm*32 + am*16 + (lane >> 2);
            float2 v0; v0.x = cacc[am][na][0] + bx; v0.y = cacc[am][na][1] + by;
            float2 v1; v1.x = cacc[am][na][2] + bx; v1.y = cacc[am][na][3] + by;
            *(float2*)&g_pre[(size_t)r * 3072 + ngl]       = v0;
            *(float2*)&g_pre[(size_t)(r + 8) * 3072 + ngl] = v1;
        }
    }
}

// ---------------------------------------------------------------------------
// Kernel 2: persistent BiLSTM recurrence (fp32). 128 blocks x 128 thr.
// ---------------------------------------------------------------------------
__device__ __forceinline__ float sigf(float x) { return 1.f / (1.f + expf(-x)); }

#define REC_SMEM_FLOATS (96*388 + 384*16 + 96*17 + 384)

__device__ __forceinline__ void fma_row(float acc[4], float4 w,
                                        float4 ha, float4 hb, float4 hc, float4 hd)
{
    acc[0] = fmaf(w.w, hd.x, fmaf(w.z, hc.x, fmaf(w.y, hb.x, fmaf(w.x, ha.x, acc[0]))));
    acc[1] = fmaf(w.w, hd.y, fmaf(w.z, hc.y, fmaf(w.y, hb.y, fmaf(w.x, ha.y, acc[1]))));
    acc[2] = fmaf(w.w, hd.z, fmaf(w.z, hc.z, fmaf(w.y, hb.z, fmaf(w.x, ha.z, acc[2]))));
    acc[3] = fmaf(w.w, hd.w, fmaf(w.z, hc.w, fmaf(w.y, hb.w, fmaf(w.x, ha.w, acc[3]))));
}

__global__ __launch_bounds__(128) void k_rec(
    const float* __restrict__ whf, const float* __restrict__ whb,
    const float* __restrict__ h0, const float* __restrict__ c0)
{
    extern __shared__ float sm[];
    float* w_s    = sm;                       // [96][388]
    float* h_s    = sm + 96*388;              // [384][16]
    float* gate_s = h_s + 384*16;             // [96][17]
    float* c_s    = gate_s + 96*17;           // [24*16]

    const int bid = blockIdx.x;
    const int dir = bid >> 6;
    const int kg  = (bid >> 2) & 15;
    const int bg  = bid & 3;
    const int k0  = kg * 24, b0 = bg * 16;
    const int tid = threadIdx.x;
    const float* whh = dir ? whb : whf;

    for (int idx = tid; idx < 96*96; idx += 128) {
        int r = idx / 96, cq = (idx - r*96) * 4;
        int gate = r / 24, kk = r - gate*24;
        float4 v = *(const float4*)(whh + (size_t)(gate*384 + k0 + kk) * 384 + cq);
        *(float4*)&w_s[r*388 + cq] = v;
    }
    for (int idx = tid; idx < 384; idx += 128) {
        int kk = idx >> 4, b = idx & 15;
        c_s[idx] = c0[((size_t)dir*64 + b0 + b) * 384 + k0 + kk];
    }
    __syncthreads();

    const int rg = tid >> 2;
    const int bq = tid & 3;
    const float* wr0 = w_s + (3*rg + 0) * 388;
    const float* wr1 = w_s + (3*rg + 1) * 388;
    const float* wr2 = w_s + (3*rg + 2) * 388;
    int grow[3];
#pragma unroll
    for (int i = 0; i < 3; i++) {
        int r = 3*rg + i;
        grow[i] = dir*1536 + (r/24)*384 + k0 + (r - (r/24)*24);
    }
    volatile unsigned int* bar = &g_bar[dir*4 + bg];

    // preload gate pre-activations for the first step
    float acc[3][4];
    {
        const int t0 = dir ? 511 : 0;
#pragma unroll
        for (int i = 0; i < 3; i++)
#pragma unroll
            for (int j = 0; j < 4; j++)
                acc[i][j] = g_pre[((size_t)t0*64 + b0 + 4*bq + j) * 3072 + grow[i]];
    }

    for (int s = 0; s < 512; s++) {
        const int t = dir ? (511 - s) : s;

        if (s == 0) {
            for (int idx = tid; idx < 384*16; idx += 128) {
                int k = idx >> 4, b = idx & 15;
                h_s[idx] = h0[((size_t)dir*64 + b0 + b) * 384 + k];
            }
        } else {
            const int tp = dir ? (t + 1) : (t - 1);
            const float* hp = &g_h[dir][tp][0][b0];
            for (int idx = tid; idx < 384*4; idx += 128) {
                int k = idx >> 2, q = idx & 3;
                float4 v = *(const float4*)(hp + (size_t)k*64 + q*4);
                *(float4*)&h_s[k*16 + q*4] = v;
            }
        }
        __syncthreads();

#pragma unroll 2
        for (int k = 0; k < 384; k += 4) {
            float4 w0 = *(const float4*)(wr0 + k);
            float4 w1 = *(const float4*)(wr1 + k);
            float4 w2 = *(const float4*)(wr2 + k);
            float4 ha = *(const float4*)&h_s[(k+0)*16 + bq*4];
            float4 hb = *(const float4*)&h_s[(k+1)*16 + bq*4];
            float4 hc = *(const float4*)&h_s[(k+2)*16 + bq*4];
            float4 hd = *(const float4*)&h_s[(k+3)*16 + bq*4];
            fma_row(acc[0], w0, ha, hb, hc, hd);
            fma_row(acc[1], w1, ha, hb, hc, hd);
            fma_row(acc[2], w2, ha, hb, hc, hd);
        }
#pragma unroll
        for (int i = 0; i < 3; i++)
#pragma unroll
            for (int j = 0; j < 4; j++)
                gate_s[(3*rg + i)*17 + 4*bq + j] = acc[i][j];
        __syncthreads();

        for (int idx = tid; idx < 384; idx += 128) {
            int kk = idx >> 4, b = idx & 15;
            float gi = gate_s[(kk     )*17 + b];
            float gf = gate_s[(kk + 24)*17 + b];
            float gg = gate_s[(kk + 48)*17 + b];
            float go = gate_s[(kk + 72)*17 + b];
            float c = sigf(gf) * c_s[idx] + sigf(gi) * tanhf(gg);
            c_s[idx] = c;
            g_h[dir][t][k0 + kk][b0 + b] = sigf(go) * tanhf(c);
        }
        __threadfence();
        __syncthreads();

        if (tid == 0) atomicAdd((unsigned int*)&g_bar[dir*4 + bg], 1u);

        // hide next step's g_pre latency behind the barrier
        if (s + 1 < 512) {
            const int tn = dir ? (510 - s) : (s + 1);
#pragma unroll
            for (int i = 0; i < 3; i++)
#pragma unroll
                for (int j = 0; j < 4; j++)
                    acc[i][j] = g_pre[((size_t)tn*64 + b0 + 4*bq + j) * 3072 + grow[i]];
        }

        if (tid == 0) {
            const unsigned int target = 16u * (unsigned)(s + 1);
            while (*bar < target) { }
            __threadfence();
        }
        __syncthreads();
    }
}

// ---------------------------------------------------------------------------
// Kernel 3: emissions (4 independent accumulator chains for MLP)
// ---------------------------------------------------------------------------
__global__ __launch_bounds__(256) void k_fc(const float* __restrict__ fcw,
                                            const float* __restrict__ fcb)
{
    __shared__ float wsh[12*768];
    __shared__ float bsh[12];
    const int t = blockIdx.x;
    const int tid = threadIdx.x;
    for (int i = tid; i < 12*768; i += 256) wsh[i] = fcw[i];
    if (tid < 12) bsh[tid] = fcb[tid];
    __syncthreads();

    for (int o = tid; o < 768; o += 256) {
        int l = o >> 6, b = o & 63;
        const float* wl  = &wsh[l*768];
        const float* hp0 = &g_h[0][t][0][b];
        const float* hp1 = &g_h[1][t][0][b];
        float s0 = 0.f, s1 = 0.f, s2 = 0.f, s3 = 0.f;
#pragma unroll 4
        for (int k = 0; k < 384; k += 4) {
            s0 = fmaf(hp0[(size_t)(k+0)*64], wl[k+0], s0);
            s1 = fmaf(hp0[(size_t)(k+1)*64], wl[k+1], s1);
            s2 = fmaf(hp0[(size_t)(k+2)*64], wl[k+2], s2);
            s3 = fmaf(hp0[(size_t)(k+3)*64], wl[k+3], s3);
        }
#pragma unroll 4
        for (int k = 0; k < 384; k += 4) {
            s0 = fmaf(hp1[(size_t)(k+0)*64], wl[384+k+0], s0);
            s1 = fmaf(hp1[(size_t)(k+1)*64], wl[384+k+1], s1);
            s2 = fmaf(hp1[(size_t)(k+2)*64], wl[384+k+2], s2);
            s3 = fmaf(hp1[(size_t)(k+3)*64], wl[384+k+3], s3);
        }
        g_feat[t][b][l] = bsh[l] + ((s0 + s1) + (s2 + s3));
    }
}

// ---------------------------------------------------------------------------
// Kernel 4: Viterbi forward + backtrace (1 block, 768 threads)
// ---------------------------------------------------------------------------
__global__ __launch_bounds__(768) void k_vit(const float* __restrict__ trans,
                                             const int* __restrict__ start_idx,
                                             float* __restrict__ out)
{
    __shared__ float fvbuf[2][64][12];
    __shared__ float tr[12][12];
    const int tid = threadIdx.x;
    const int b = tid / 12, l = tid - b*12;

    if (tid < 144) tr[tid / 12][tid % 12] = trans[tid];
    const int s0 = *start_idx;
    fvbuf[0][b][l] = (l == s0) ? 0.f : NEGV;
    __syncthreads();

    float ft_next = g_feat[1][b][l];
    for (int t = 1; t < 512; t++) {
        const float* fv = fvbuf[(t - 1) & 1][b];
        float ft = ft_next;
        if (t < 511) ft_next = g_feat[t + 1][b][l];
        float best = tr[l][0] + fv[0];
        int arg = 0;
#pragma unroll
        for (int p = 1; p < 12; p++) {
            float sc = tr[l][p] + fv[p];
            if (sc > best) { best = sc; arg = p; }
        }
        fvbuf[t & 1][b][l] = best + ft;
        g_ptr[t - 1][b][l] = (unsigned char)arg;
        __syncthreads();
    }

    if (tid < 64) {
        const int bb = tid;
        float best = fvbuf[1][bb][0];
        int last = 0;
#pragma unroll
        for (int p = 1; p < 12; p++)
            if (fvbuf[1][bb][p] > best) { best = fvbuf[1][bb][p]; last = p; }
        out[bb] = best;
        float* path = out + 64 + (size_t)bb * 512;
        int cur = last;
        path[511] = (float)cur;
        for (int t = 510; t >= 0; t--) {
            cur = g_ptr[t][bb][cur];
            path[t] = (float)cur;
        }
    }
}

// ---------------------------------------------------------------------------
extern "C" void kernel_launch(void* const* d_in, const int* in_sizes, int n_in,
                              void* d_out, int out_size)
{
    const float* hs   = (const float*)d_in[0];
    const float* h0   = (const float*)d_in[1];
    const float* c0   = (const float*)d_in[2];
    const float* wihf = (const float*)d_in[3];
    const float* whhf = (const float*)d_in[4];
    const float* bihf = (const float*)d_in[5];
    const float* bhhf = (const float*)d_in[6];
    const float* wihb = (const float*)d_in[7];
    const float* whhb = (const float*)d_in[8];
    const float* bihb = (const float*)d_in[9];
    const float* bhhb = (const float*)d_in[10];
    const float* fcw  = (const float*)d_in[11];
    const float* fcb  = (const float*)d_in[12];
    const float* trans= (const float*)d_in[13];
    const int*   stp  = (const int*)d_in[14];
    (void)in_sizes; (void)n_in; (void)out_size;

    static int attr_set = 0;
    const size_t rec_smem  = (size_t)REC_SMEM_FLOATS * sizeof(float); // 181,632 B
    const size_t gemm_smem = 8192 * sizeof(float4);                   // 131,072 B
    cudaFuncSetAttribute(k_rec,  cudaFuncAttributeMaxDynamicSharedMemorySize, (int)rec_smem);
    cudaFuncSetAttribute(k_gemm, cudaFuncAttributeMaxDynamicSharedMemorySize, (int)gemm_smem);
    (void)attr_set;

    k_init<<<1, 32>>>();

    dim3 gg(24, 256);
    k_gemm<<<gg, 256, gemm_smem>>>(hs, wihf, wihb, bihf, bhhf, bihb, bhhb);

    k_rec<<<128, 128, rec_smem>>>(whhf, whhb, h0, c0);

    k_fc<<<512, 256>>>(fcw, fcb);

    k_vit<<<1, 768>>>(trans, stp, (float*)d_out);
}